// round 10
// baseline (speedup 1.0000x reference)
#include <cuda_runtime.h>
#include <cuda_bf16.h>
#include <math.h>

// ---------------------------------------------------------------------------
// Problem constants
// ---------------------------------------------------------------------------
#define T_STEPS 512          // L*N = 64*8
#define HDIM    1024
#define GDIM    4096         // 4*H
#define VOCAB   32000
#define NCTA    128          // recurrence CTAs (<= 148 SMs -> all co-resident)

// ---------------------------------------------------------------------------
// Device scratch (static allocation allowed; cudaMalloc is not)
// ---------------------------------------------------------------------------
__device__ float g_seq[T_STEPS * HDIM];     // 2 MB  embedding sequence
__device__ float g_X  [T_STEPS * GDIM];     // 8 MB  precomputed W_ih@x + biases
__device__ float g_H0 [T_STEPS * HDIM];     // 2 MB  layer-0 hidden states
__device__ float g_H1 [T_STEPS * HDIM];     // 2 MB  layer-1 hidden states
// 8 spread barrier counters, 512B apart (distinct addresses / mostly distinct
// LTS slices). Monotone: counter[j] == 16*(t+1) after all its CTAs pass step t.
__device__ __align__(4096) unsigned g_bar8[8 * 128];

// ---------------------------------------------------------------------------
// f32x2 packed-FMA helpers (sm_100+)
// ---------------------------------------------------------------------------
__device__ __forceinline__ unsigned long long pack2(float lo, float hi) {
    unsigned long long r;
    asm("mov.b64 %0, {%1, %2};" : "=l"(r) : "f"(lo), "f"(hi));
    return r;
}
__device__ __forceinline__ void unpack2(unsigned long long v, float& lo, float& hi) {
    asm("mov.b64 {%0, %1}, %2;" : "=f"(lo), "=f"(hi) : "l"(v));
}
__device__ __forceinline__ unsigned long long fma2(unsigned long long a,
                                                   unsigned long long b,
                                                   unsigned long long c) {
    unsigned long long d;
    asm("fma.rn.f32x2 %0, %1, %2, %3;" : "=l"(d) : "l"(a), "l"(b), "l"(c));
    return d;
}

// fast sigmoid via MUFU; tanh(x) = 2*sigmoid(2x) - 1
__device__ __forceinline__ float fsig(float x) {
    return __fdividef(1.f, 1.f + __expf(-x));
}

// ---------------------------------------------------------------------------
// Embedding gather: seq[t] = emb[x[n, l]],  t = l*8 + n
// ---------------------------------------------------------------------------
__global__ void embed_kernel(const int* __restrict__ x, const float* __restrict__ emb) {
    int t = blockIdx.x;
    int n = t & 7;
    int l = t >> 3;
    int tok = x[n * 64 + l];
    const float4* src = (const float4*)(emb + (size_t)tok * HDIM);
    ((float4*)(g_seq + (size_t)t * HDIM))[threadIdx.x] = src[threadIdx.x];
}

__global__ void reset_bar8_kernel() {
    g_bar8[threadIdx.x] = 0u;      // 1024 threads clear whole array
}

// ---------------------------------------------------------------------------
// NT GEMM:  C = A @ B^T + bias1 (+ bias2).  128x128x16 tiles, f32x2 FMA.
// ---------------------------------------------------------------------------
__global__ void __launch_bounds__(256, 2) gemm_nt_bias(
    const float* __restrict__ A, const float* __restrict__ B,
    const float* __restrict__ bias1, const float* __restrict__ bias2,
    float* __restrict__ C, int M, int N, int K)
{
    __shared__ float As[16][128];
    __shared__ float Bs[16][128];

    const int tid = threadIdx.x;
    const int tx = tid & 15;
    const int ty = tid >> 4;
    const int bm = blockIdx.y * 128;
    const int bn = blockIdx.x * 128;

    unsigned long long acc[8][4];
    #pragma unroll
    for (int i = 0; i < 8; i++)
        #pragma unroll
        for (int j = 0; j < 4; j++) acc[i][j] = 0ull;

    for (int k0 = 0; k0 < K; k0 += 16) {
        #pragma unroll
        for (int i = 0; i < 2; i++) {
            int chunk = tid * 2 + i;
            int ar = chunk >> 2;
            int ac = chunk & 3;
            float4 v = *(const float4*)(A + (size_t)(bm + ar) * K + k0 + ac * 4);
            As[ac * 4 + 0][ar] = v.x; As[ac * 4 + 1][ar] = v.y;
            As[ac * 4 + 2][ar] = v.z; As[ac * 4 + 3][ar] = v.w;
            float4 u = *(const float4*)(B + (size_t)(bn + ar) * K + k0 + ac * 4);
            Bs[ac * 4 + 0][ar] = u.x; Bs[ac * 4 + 1][ar] = u.y;
            Bs[ac * 4 + 2][ar] = u.z; Bs[ac * 4 + 3][ar] = u.w;
        }
        __syncthreads();

        #pragma unroll
        for (int kk = 0; kk < 16; kk++) {
            float4 a0 = *(const float4*)&As[kk][ty * 8];
            float4 a1 = *(const float4*)&As[kk][ty * 8 + 4];
            const unsigned long long* bp = (const unsigned long long*)&Bs[kk][tx * 8];
            unsigned long long b2[4];
            #pragma unroll
            for (int j = 0; j < 4; j++) b2[j] = bp[j];
            float a[8] = {a0.x, a0.y, a0.z, a0.w, a1.x, a1.y, a1.z, a1.w};
            #pragma unroll
            for (int i = 0; i < 8; i++) {
                unsigned long long a2 = pack2(a[i], a[i]);
                #pragma unroll
                for (int j = 0; j < 4; j++) acc[i][j] = fma2(a2, b2[j], acc[i][j]);
            }
        }
        __syncthreads();
    }

    #pragma unroll
    for (int i = 0; i < 8; i++) {
        int m = bm + ty * 8 + i;
        float* crow = C + (size_t)m * N + bn + tx * 8;
        #pragma unroll
        for (int j = 0; j < 4; j++) {
            float lo, hi;
            unpack2(acc[i][j], lo, hi);
            int n = bn + tx * 8 + 2 * j;
            lo += bias1[n];
            hi += bias1[n + 1];
            if (bias2) { lo += bias2[n]; hi += bias2[n + 1]; }
            *(float2*)(crow + 2 * j) = make_float2(lo, hi);
        }
    }
}

// ---------------------------------------------------------------------------
// LSTM recurrence, register-resident weights + spread atomic barrier.
// Sync recipe is EXACTLY round-4's proven one (atomicAdd arrival + volatile-
// load polling + threadfences), but arrival is spread across 8 counter
// addresses so the LTS atomic ALU serializes 16 RMWs per address, not 128.
// ---------------------------------------------------------------------------
__global__ void __launch_bounds__(256) lstm_recur_kernel(
    const float* __restrict__ Xpre,      // [512*4096] ih part + both biases
    const float* __restrict__ Whh,       // [4096*1024]
    float* __restrict__ Hout,            // [512*1024]
    float* __restrict__ out_h,           // [1024] or null
    float* __restrict__ out_c)           // [1024] or null
{
    __shared__ float h_s[HDIM];              // current hidden state
    __shared__ float part_s[32 * 9];         // partials, stride 9 (conflict-free)
    __shared__ float xp_s[32];               // current step's X values for this CTA

    const int tid  = threadIdx.x;
    const int cta  = blockIdx.x;             // 0..127
    const int hb   = cta * 8;
    const int lane = tid & 31;               // row rr
    const int wrp  = tid >> 5;               // h-chunk

    // Row rr -> global row gate*1024 + hb + k   (rr = gate*8 + k)
    const int gate = lane >> 3, k = lane & 7;
    const float* wrow = Whh + (size_t)(gate * 1024 + hb + k) * HDIM + wrp * 128;

    // Load 128 weights into registers as 64 packed f32x2
    unsigned long long w2[64];
    #pragma unroll
    for (int i = 0; i < 32; i++) {
        float4 v = ((const float4*)wrow)[i];
        w2[2 * i]     = pack2(v.x, v.y);
        w2[2 * i + 1] = pack2(v.z, v.w);
    }

    ((float4*)h_s)[tid] = make_float4(0.f, 0.f, 0.f, 0.f);
    float c_reg = 0.f;

    // Preload X[0] for this CTA
    float x_next = 0.f;
    if (tid < 32)
        x_next = Xpre[(tid >> 3) * 1024 + hb + (tid & 7)];
    __syncthreads();

    const float4* h4 = (const float4*)h_s;

    for (int t = 0; t < T_STEPS; t++) {
        // publish this step's X, prefetch next step's
        if (tid < 32) {
            xp_s[tid] = x_next;
            if (t + 1 < T_STEPS)
                x_next = Xpre[(size_t)(t + 1) * GDIM + (tid >> 3) * 1024 + hb + (tid & 7)];
        }

        // matvec chunk: dot(W_row[128w..], h[128w..]), 4 accumulators
        unsigned long long a0 = 0ull, a1 = 0ull, a2 = 0ull, a3 = 0ull;
        #pragma unroll
        for (int i = 0; i < 32; i += 2) {
            float4 hv0 = h4[wrp * 32 + i];
            float4 hv1 = h4[wrp * 32 + i + 1];
            a0 = fma2(w2[2 * i],     pack2(hv0.x, hv0.y), a0);
            a1 = fma2(w2[2 * i + 1], pack2(hv0.z, hv0.w), a1);
            a2 = fma2(w2[2 * i + 2], pack2(hv1.x, hv1.y), a2);
            a3 = fma2(w2[2 * i + 3], pack2(hv1.z, hv1.w), a3);
        }
        float l0, h0, l1, h1, l2, h2, l3, h3;
        unpack2(a0, l0, h0); unpack2(a1, l1, h1);
        unpack2(a2, l2, h2); unpack2(a3, l3, h3);
        part_s[lane * 9 + wrp] = ((l0 + h0) + (l1 + h1)) + ((l2 + h2) + (l3 + h3));
        __syncthreads();

        // activations: thread k (0..7) handles h-index hb+k
        if (tid < 8) {
            float s[4];
            #pragma unroll
            for (int g = 0; g < 4; g++) {
                int rr = g * 8 + tid;
                float v = xp_s[rr];
                #pragma unroll
                for (int w = 0; w < 8; w++) v += part_s[rr * 9 + w];
                s[g] = v;
            }
            float i_ = fsig(s[0]);
            float f_ = fsig(s[1]);
            float g_ = 2.f * fsig(2.f * s[2]) - 1.f;     // tanh
            float o_ = fsig(s[3]);
            c_reg = f_ * c_reg + i_ * g_;
            float h_new = o_ * (2.f * fsig(2.f * c_reg) - 1.f);
            Hout[(size_t)t * HDIM + hb + tid] = h_new;
            if (t == T_STEPS - 1) {
                if (out_h) out_h[hb + tid] = h_new;
                if (out_c) out_c[hb + tid] = c_reg;
            }
            __threadfence();   // publish h before barrier arrival (round-4 proven)
        }
        __syncthreads();

        // arrival: atomic RMW at the LTS (unconditionally globally visible),
        // spread over 8 addresses -> 16-deep serialization instead of 128.
        if (tid == 0)
            atomicAdd(&g_bar8[(cta & 7) * 128], 1u);

        // detection: warp 0 volatile-polls the 8 counters (round-4 proven load
        // path). counter[j] is monotone; target = 16*(t+1).
        if (tid < 32) {
            const unsigned tgt = 16u * (unsigned)(t + 1);
            volatile unsigned* ctr = &g_bar8[(lane & 7) * 128];
            for (;;) {
                bool ok = (*ctr >= tgt);
                if (__all_sync(0xffffffffu, ok)) break;
            }
            __threadfence();   // consumer-side: order h reads after poll success
        }
        __syncthreads();

        // reload full h(t): per-step-fresh addresses -> L1 miss -> L2 (coherent)
        ((float4*)h_s)[tid] = ((const float4*)(Hout + (size_t)t * HDIM))[tid];
        __syncthreads();
    }
}

// ---------------------------------------------------------------------------
// Launch
// ---------------------------------------------------------------------------
extern "C" void kernel_launch(void* const* d_in, const int* in_sizes, int n_in,
                              void* d_out, int out_size) {
    const int*   x    = (const int*)  d_in[0];
    const float* emb  = (const float*)d_in[1];
    const float* W_ih = (const float*)d_in[2];
    const float* W_hh = (const float*)d_in[3];
    const float* b_ih = (const float*)d_in[4];
    const float* b_hh = (const float*)d_in[5];
    const float* W_fc = (const float*)d_in[6];
    const float* b_fc = (const float*)d_in[7];

    float* out        = (float*)d_out;
    float* out_scores = out;
    const size_t SC   = (size_t)T_STEPS * VOCAB;
    bool  has_state   = ((size_t)out_size >= SC + 4096);
    float* out_h      = has_state ? out + SC        : nullptr;
    float* out_c      = has_state ? out + SC + 2048 : nullptr;

    void *p_seq, *p_X, *p_H0, *p_H1;
    cudaGetSymbolAddress(&p_seq, g_seq);
    cudaGetSymbolAddress(&p_X,   g_X);
    cudaGetSymbolAddress(&p_H0,  g_H0);
    cudaGetSymbolAddress(&p_H1,  g_H1);
    float* seq = (float*)p_seq;
    float* X   = (float*)p_X;
    float* H0  = (float*)p_H0;
    float* H1  = (float*)p_H1;

    const size_t WSZ = (size_t)GDIM * HDIM;

    embed_kernel<<<T_STEPS, 256>>>(x, emb);

    gemm_nt_bias<<<dim3(GDIM / 128, T_STEPS / 128), 256>>>(
        seq, W_ih, b_ih, b_hh, X, T_STEPS, GDIM, HDIM);

    reset_bar8_kernel<<<1, 1024>>>();
    lstm_recur_kernel<<<NCTA, 256>>>(X, W_hh, H0, out_h, out_c);

    gemm_nt_bias<<<dim3(GDIM / 128, T_STEPS / 128), 256>>>(
        H0, W_ih + WSZ, b_ih + GDIM, b_hh + GDIM, X, T_STEPS, GDIM, HDIM);

    reset_bar8_kernel<<<1, 1024>>>();
    lstm_recur_kernel<<<NCTA, 256>>>(X, W_hh + WSZ, H1,
                                     out_h ? out_h + HDIM : nullptr,
                                     out_c ? out_c + HDIM : nullptr);

    gemm_nt_bias<<<dim3(VOCAB / 128, T_STEPS / 128), 256>>>(
        H1, W_fc, b_fc, nullptr, out_scores, T_STEPS, VOCAB, HDIM);
}

// round 12
// speedup vs baseline: 1.3812x; 1.3812x over previous
#include <cuda_runtime.h>
#include <cuda_bf16.h>
#include <math.h>

// ---------------------------------------------------------------------------
// Problem constants
// ---------------------------------------------------------------------------
#define T_STEPS 512          // L*N = 64*8
#define HDIM    1024
#define GDIM    4096         // 4*H
#define VOCAB   32000
#define NCTA    128          // recurrence CTAs (<= 148 SMs -> all co-resident)

#define CANARY_U 0x7fc00001u // NaN bit pattern; h = o*tanh(c) can never be NaN

// ---------------------------------------------------------------------------
// Device scratch (static allocation allowed; cudaMalloc is not)
// ---------------------------------------------------------------------------
__device__ float g_seq[T_STEPS * HDIM];     // 2 MB  embedding sequence
__device__ float g_X  [T_STEPS * GDIM];     // 8 MB  precomputed W_ih@x + biases
__device__ float g_H0 [T_STEPS * HDIM];     // 2 MB  layer-0 hidden states
__device__ float g_H1 [T_STEPS * HDIM];     // 2 MB  layer-1 hidden states

// ---------------------------------------------------------------------------
// f32x2 packed-FMA helpers (sm_100+)
// ---------------------------------------------------------------------------
__device__ __forceinline__ unsigned long long pack2(float lo, float hi) {
    unsigned long long r;
    asm("mov.b64 %0, {%1, %2};" : "=l"(r) : "f"(lo), "f"(hi));
    return r;
}
__device__ __forceinline__ void unpack2(unsigned long long v, float& lo, float& hi) {
    asm("mov.b64 {%0, %1}, %2;" : "=f"(lo), "=f"(hi) : "l"(v));
}
__device__ __forceinline__ unsigned long long fma2(unsigned long long a,
                                                   unsigned long long b,
                                                   unsigned long long c) {
    unsigned long long d;
    asm("fma.rn.f32x2 %0, %1, %2, %3;" : "=l"(d) : "l"(a), "l"(b), "l"(c));
    return d;
}

// fast sigmoid via MUFU; tanh(x) = 2*sigmoid(2x) - 1
__device__ __forceinline__ float fsig(float x) {
    return __fdividef(1.f, 1.f + __expf(-x));
}

// ---------------------------------------------------------------------------
// Canary fill for H0/H1 (runs inside the graph, before each recurrence pass)
// ---------------------------------------------------------------------------
__global__ void canary_kernel() {
    unsigned idx = blockIdx.x * blockDim.x + threadIdx.x;   // 512*256 = 131072
    float c = __uint_as_float(CANARY_U);
    float4 cv = make_float4(c, c, c, c);
    ((float4*)g_H0)[idx] = cv;
    ((float4*)g_H1)[idx] = cv;
}

// ---------------------------------------------------------------------------
// Embedding gather: seq[t] = emb[x[n, l]],  t = l*8 + n
// ---------------------------------------------------------------------------
__global__ void embed_kernel(const int* __restrict__ x, const float* __restrict__ emb) {
    int t = blockIdx.x;
    int n = t & 7;
    int l = t >> 3;
    int tok = x[n * 64 + l];
    const float4* src = (const float4*)(emb + (size_t)tok * HDIM);
    ((float4*)(g_seq + (size_t)t * HDIM))[threadIdx.x] = src[threadIdx.x];
}

// ---------------------------------------------------------------------------
// NT GEMM:  C = A @ B^T + bias1 (+ bias2).  128x128x16 tiles, f32x2 FMA.
// ---------------------------------------------------------------------------
__global__ void __launch_bounds__(256, 2) gemm_nt_bias(
    const float* __restrict__ A, const float* __restrict__ B,
    const float* __restrict__ bias1, const float* __restrict__ bias2,
    float* __restrict__ C, int M, int N, int K)
{
    __shared__ float As[16][128];
    __shared__ float Bs[16][128];

    const int tid = threadIdx.x;
    const int tx = tid & 15;
    const int ty = tid >> 4;
    const int bm = blockIdx.y * 128;
    const int bn = blockIdx.x * 128;

    unsigned long long acc[8][4];
    #pragma unroll
    for (int i = 0; i < 8; i++)
        #pragma unroll
        for (int j = 0; j < 4; j++) acc[i][j] = 0ull;

    for (int k0 = 0; k0 < K; k0 += 16) {
        #pragma unroll
        for (int i = 0; i < 2; i++) {
            int chunk = tid * 2 + i;
            int ar = chunk >> 2;
            int ac = chunk & 3;
            float4 v = *(const float4*)(A + (size_t)(bm + ar) * K + k0 + ac * 4);
            As[ac * 4 + 0][ar] = v.x; As[ac * 4 + 1][ar] = v.y;
            As[ac * 4 + 2][ar] = v.z; As[ac * 4 + 3][ar] = v.w;
            float4 u = *(const float4*)(B + (size_t)(bn + ar) * K + k0 + ac * 4);
            Bs[ac * 4 + 0][ar] = u.x; Bs[ac * 4 + 1][ar] = u.y;
            Bs[ac * 4 + 2][ar] = u.z; Bs[ac * 4 + 3][ar] = u.w;
        }
        __syncthreads();

        #pragma unroll
        for (int kk = 0; kk < 16; kk++) {
            float4 a0 = *(const float4*)&As[kk][ty * 8];
            float4 a1 = *(const float4*)&As[kk][ty * 8 + 4];
            const unsigned long long* bp = (const unsigned long long*)&Bs[kk][tx * 8];
            unsigned long long b2[4];
            #pragma unroll
            for (int j = 0; j < 4; j++) b2[j] = bp[j];
            float a[8] = {a0.x, a0.y, a0.z, a0.w, a1.x, a1.y, a1.z, a1.w};
            #pragma unroll
            for (int i = 0; i < 8; i++) {
                unsigned long long a2 = pack2(a[i], a[i]);
                #pragma unroll
                for (int j = 0; j < 4; j++) acc[i][j] = fma2(a2, b2[j], acc[i][j]);
            }
        }
        __syncthreads();
    }

    #pragma unroll
    for (int i = 0; i < 8; i++) {
        int m = bm + ty * 8 + i;
        float* crow = C + (size_t)m * N + bn + tx * 8;
        #pragma unroll
        for (int j = 0; j < 4; j++) {
            float lo, hi;
            unpack2(acc[i][j], lo, hi);
            int n = bn + tx * 8 + 2 * j;
            lo += bias1[n];
            hi += bias1[n + 1];
            if (bias2) { lo += bias2[n]; hi += bias2[n + 1]; }
            *(float2*)(crow + 2 * j) = make_float2(lo, hi);
        }
    }
}

// ---------------------------------------------------------------------------
// LSTM recurrence: register-resident weights, BARRIER-FREE exchange.
// The data is the flag: Hout is pre-filled with a NaN canary; producers
// publish h via atomicExch (performed at the LTS -> immediately globally
// visible); consumers poll the h values directly with ld.volatile until
// non-canary. No fence, no counters, no separate reload.
// 128 CTAs x 256 threads; CTA c owns h-indices [8c, 8c+8) = 32 gate rows.
// ---------------------------------------------------------------------------
__global__ void __launch_bounds__(256) lstm_recur_kernel(
    const float* __restrict__ Xpre,      // [512*4096] ih part + both biases
    const float* __restrict__ Whh,       // [4096*1024]
    float* __restrict__ Hout,            // [512*1024], canary-filled
    float* __restrict__ out_h,           // [1024] or null
    float* __restrict__ out_c)           // [1024] or null
{
    __shared__ float h_s[HDIM];              // current hidden state
    __shared__ float part_s[32 * 9];         // partials, stride 9 (conflict-free)
    __shared__ float xp_s[32];               // current step's X values for this CTA

    const int tid  = threadIdx.x;
    const int cta  = blockIdx.x;             // 0..127
    const int hb   = cta * 8;
    const int lane = tid & 31;               // row rr
    const int wrp  = tid >> 5;               // h-chunk

    // Row rr -> global row gate*1024 + hb + k   (rr = gate*8 + k)
    const int gate = lane >> 3, k = lane & 7;
    const float* wrow = Whh + (size_t)(gate * 1024 + hb + k) * HDIM + wrp * 128;

    // Load 128 weights into registers as 64 packed f32x2
    unsigned long long w2[64];
    #pragma unroll
    for (int i = 0; i < 32; i++) {
        float4 v = ((const float4*)wrow)[i];
        w2[2 * i]     = pack2(v.x, v.y);
        w2[2 * i + 1] = pack2(v.z, v.w);
    }

    ((float4*)h_s)[tid] = make_float4(0.f, 0.f, 0.f, 0.f);
    float c_reg = 0.f;

    // Preload X[0] for this CTA
    float x_next = 0.f;
    if (tid < 32)
        x_next = Xpre[(tid >> 3) * 1024 + hb + (tid & 7)];
    __syncthreads();

    const float4* h4 = (const float4*)h_s;

    for (int t = 0; t < T_STEPS; t++) {
        // publish this step's X, prefetch next step's
        if (tid < 32) {
            xp_s[tid] = x_next;
            if (t + 1 < T_STEPS)
                x_next = Xpre[(size_t)(t + 1) * GDIM + (tid >> 3) * 1024 + hb + (tid & 7)];
        }

        // matvec chunk: dot(W_row[128w..], h[128w..]), 4 accumulators
        unsigned long long a0 = 0ull, a1 = 0ull, a2 = 0ull, a3 = 0ull;
        #pragma unroll
        for (int i = 0; i < 32; i += 2) {
            float4 hv0 = h4[wrp * 32 + i];
            float4 hv1 = h4[wrp * 32 + i + 1];
            a0 = fma2(w2[2 * i],     pack2(hv0.x, hv0.y), a0);
            a1 = fma2(w2[2 * i + 1], pack2(hv0.z, hv0.w), a1);
            a2 = fma2(w2[2 * i + 2], pack2(hv1.x, hv1.y), a2);
            a3 = fma2(w2[2 * i + 3], pack2(hv1.z, hv1.w), a3);
        }
        float l0, h0, l1, h1, l2, h2, l3, h3;
        unpack2(a0, l0, h0); unpack2(a1, l1, h1);
        unpack2(a2, l2, h2); unpack2(a3, l3, h3);
        part_s[lane * 9 + wrp] = ((l0 + h0) + (l1 + h1)) + ((l2 + h2) + (l3 + h3));
        __syncthreads();

        // activations: thread k (0..7) handles h-index hb+k, publishes via
        // atomicExch (LTS-performed -> immediately globally visible, no fence)
        if (tid < 8) {
            float s[4];
            #pragma unroll
            for (int g = 0; g < 4; g++) {
                int rr = g * 8 + tid;
                float v = xp_s[rr];
                #pragma unroll
                for (int w = 0; w < 8; w++) v += part_s[rr * 9 + w];
                s[g] = v;
            }
            float i_ = fsig(s[0]);
            float f_ = fsig(s[1]);
            float g_ = 2.f * fsig(2.f * s[2]) - 1.f;     // tanh
            float o_ = fsig(s[3]);
            c_reg = f_ * c_reg + i_ * g_;
            float h_new = o_ * (2.f * fsig(2.f * c_reg) - 1.f);
            atomicExch(&Hout[(size_t)t * HDIM + hb + tid], h_new);
            if (t == T_STEPS - 1) {
                if (out_h) out_h[hb + tid] = h_new;
                if (out_c) out_c[hb + tid] = c_reg;
            }
        }
        // NOTE: no syncthreads here — other threads may start polling early.

        // poll-reload h(t): each thread polls its own float4 of Hout[t] with
        // volatile loads (the proven poll path) until all 4 words are real.
        if (t + 1 < T_STEPS) {
            const float4* src = ((const float4*)(Hout + (size_t)t * HDIM)) + tid;
            float fx, fy, fz, fw;
            for (;;) {
                asm volatile("ld.volatile.global.v4.f32 {%0,%1,%2,%3}, [%4];"
                             : "=f"(fx), "=f"(fy), "=f"(fz), "=f"(fw)
                             : "l"(src)
                             : "memory");
                if ((__float_as_uint(fx) != CANARY_U) &
                    (__float_as_uint(fy) != CANARY_U) &
                    (__float_as_uint(fz) != CANARY_U) &
                    (__float_as_uint(fw) != CANARY_U)) break;
            }
            ((float4*)h_s)[tid] = make_float4(fx, fy, fz, fw);
        }
        __syncthreads();
    }
}

// ---------------------------------------------------------------------------
// Launch
// ---------------------------------------------------------------------------
extern "C" void kernel_launch(void* const* d_in, const int* in_sizes, int n_in,
                              void* d_out, int out_size) {
    const int*   x    = (const int*)  d_in[0];
    const float* emb  = (const float*)d_in[1];
    const float* W_ih = (const float*)d_in[2];
    const float* W_hh = (const float*)d_in[3];
    const float* b_ih = (const float*)d_in[4];
    const float* b_hh = (const float*)d_in[5];
    const float* W_fc = (const float*)d_in[6];
    const float* b_fc = (const float*)d_in[7];

    float* out        = (float*)d_out;
    float* out_scores = out;
    const size_t SC   = (size_t)T_STEPS * VOCAB;
    bool  has_state   = ((size_t)out_size >= SC + 4096);
    float* out_h      = has_state ? out + SC        : nullptr;
    float* out_c      = has_state ? out + SC + 2048 : nullptr;

    void *p_seq, *p_X, *p_H0, *p_H1;
    cudaGetSymbolAddress(&p_seq, g_seq);
    cudaGetSymbolAddress(&p_X,   g_X);
    cudaGetSymbolAddress(&p_H0,  g_H0);
    cudaGetSymbolAddress(&p_H1,  g_H1);
    float* seq = (float*)p_seq;
    float* X   = (float*)p_X;
    float* H0  = (float*)p_H0;
    float* H1  = (float*)p_H1;

    const size_t WSZ = (size_t)GDIM * HDIM;

    // canary-fill H0/H1 (inside the graph; replays re-arm it)
    canary_kernel<<<512, 256>>>();

    embed_kernel<<<T_STEPS, 256>>>(x, emb);

    gemm_nt_bias<<<dim3(GDIM / 128, T_STEPS / 128), 256>>>(
        seq, W_ih, b_ih, b_hh, X, T_STEPS, GDIM, HDIM);

    lstm_recur_kernel<<<NCTA, 256>>>(X, W_hh, H0, out_h, out_c);

    gemm_nt_bias<<<dim3(GDIM / 128, T_STEPS / 128), 256>>>(
        H0, W_ih + WSZ, b_ih + GDIM, b_hh + GDIM, X, T_STEPS, GDIM, HDIM);

    lstm_recur_kernel<<<NCTA, 256>>>(X, W_hh + WSZ, H1,
                                     out_h ? out_h + HDIM : nullptr,
                                     out_c ? out_c + HDIM : nullptr);

    gemm_nt_bias<<<dim3(VOCAB / 128, T_STEPS / 128), 256>>>(
        H1, W_fc, b_fc, nullptr, out_scores, T_STEPS, VOCAB, HDIM);
}

// round 14
// speedup vs baseline: 1.7022x; 1.2324x over previous
#include <cuda_runtime.h>
#include <cuda_bf16.h>
#include <math.h>

// ---------------------------------------------------------------------------
// Problem constants
// ---------------------------------------------------------------------------
#define T_STEPS 512          // L*N = 64*8
#define HDIM    1024
#define GDIM    4096         // 4*H
#define VOCAB   32000
#define NCTA    128          // recurrence CTAs (<= 148 SMs -> all co-resident)

#define CANARY_U 0x7fc00001u // NaN bit pattern; h = o*tanh(c) can never be NaN

// ---------------------------------------------------------------------------
// Device scratch (static allocation allowed; cudaMalloc is not)
// ---------------------------------------------------------------------------
__device__ float g_seq[T_STEPS * HDIM];     // 2 MB  embedding sequence
__device__ float g_X  [T_STEPS * GDIM];     // 8 MB  precomputed W_ih@x + biases
__device__ float g_H0 [T_STEPS * HDIM];     // 2 MB  layer-0 hidden states
__device__ float g_H1 [T_STEPS * HDIM];     // 2 MB  layer-1 hidden states

// ---------------------------------------------------------------------------
// f32x2 packed-FMA helpers (sm_100+)
// ---------------------------------------------------------------------------
__device__ __forceinline__ unsigned long long pack2(float lo, float hi) {
    unsigned long long r;
    asm("mov.b64 %0, {%1, %2};" : "=l"(r) : "f"(lo), "f"(hi));
    return r;
}
__device__ __forceinline__ void unpack2(unsigned long long v, float& lo, float& hi) {
    asm("mov.b64 {%0, %1}, %2;" : "=f"(lo), "=f"(hi) : "l"(v));
}
__device__ __forceinline__ unsigned long long fma2(unsigned long long a,
                                                   unsigned long long b,
                                                   unsigned long long c) {
    unsigned long long d;
    asm("fma.rn.f32x2 %0, %1, %2, %3;" : "=l"(d) : "l"(a), "l"(b), "l"(c));
    return d;
}

// fast sigmoid via MUFU; tanh(x) = 2*sigmoid(2x) - 1
__device__ __forceinline__ float fsig(float x) {
    return __fdividef(1.f, 1.f + __expf(-x));
}

// ---------------------------------------------------------------------------
// Canary fill for H0/H1 (runs inside the graph; replays re-arm it)
// ---------------------------------------------------------------------------
__global__ void canary_kernel() {
    unsigned idx = blockIdx.x * blockDim.x + threadIdx.x;   // 512*256 float4s
    float c = __uint_as_float(CANARY_U);
    float4 cv = make_float4(c, c, c, c);
    ((float4*)g_H0)[idx] = cv;
    ((float4*)g_H1)[idx] = cv;
}

// ---------------------------------------------------------------------------
// Embedding gather: seq[t] = emb[x[n, l]],  t = l*8 + n
// ---------------------------------------------------------------------------
__global__ void embed_kernel(const int* __restrict__ x, const float* __restrict__ emb) {
    int t = blockIdx.x;
    int n = t & 7;
    int l = t >> 3;
    int tok = x[n * 64 + l];
    const float4* src = (const float4*)(emb + (size_t)tok * HDIM);
    ((float4*)(g_seq + (size_t)t * HDIM))[threadIdx.x] = src[threadIdx.x];
}

// ---------------------------------------------------------------------------
// NT GEMM:  C = A @ B^T + bias1 (+ bias2).  128x128x16 tiles, f32x2 FMA,
// software-pipelined global loads (next K-tile prefetched into registers
// while current tile computes -> LDG latency hidden).
// ---------------------------------------------------------------------------
__global__ void __launch_bounds__(256, 2) gemm_nt_bias(
    const float* __restrict__ A, const float* __restrict__ B,
    const float* __restrict__ bias1, const float* __restrict__ bias2,
    float* __restrict__ C, int M, int N, int K)
{
    __shared__ float As[16][128];
    __shared__ float Bs[16][128];

    const int tid = threadIdx.x;
    const int tx = tid & 15;
    const int ty = tid >> 4;
    const int bm = blockIdx.y * 128;
    const int bn = blockIdx.x * 128;

    const int chunk0 = tid * 2;
    const int ar0 = chunk0 >> 2,       ac0 = chunk0 & 3;
    const int ar1 = (chunk0 + 1) >> 2, ac1 = (chunk0 + 1) & 3;
    const float* a0p = A + (size_t)(bm + ar0) * K + ac0 * 4;
    const float* a1p = A + (size_t)(bm + ar1) * K + ac1 * 4;
    const float* b0p = B + (size_t)(bn + ar0) * K + ac0 * 4;
    const float* b1p = B + (size_t)(bn + ar1) * K + ac1 * 4;

    unsigned long long acc[8][4];
    #pragma unroll
    for (int i = 0; i < 8; i++)
        #pragma unroll
        for (int j = 0; j < 4; j++) acc[i][j] = 0ull;

    // prefetch tile 0 into registers
    float4 pa0 = *(const float4*)(a0p);
    float4 pa1 = *(const float4*)(a1p);
    float4 pb0 = *(const float4*)(b0p);
    float4 pb1 = *(const float4*)(b1p);

    const int nIter = K >> 4;
    for (int it = 0; it < nIter; it++) {
        // stage registers -> smem (transposed)
        As[ac0 * 4 + 0][ar0] = pa0.x; As[ac0 * 4 + 1][ar0] = pa0.y;
        As[ac0 * 4 + 2][ar0] = pa0.z; As[ac0 * 4 + 3][ar0] = pa0.w;
        As[ac1 * 4 + 0][ar1] = pa1.x; As[ac1 * 4 + 1][ar1] = pa1.y;
        As[ac1 * 4 + 2][ar1] = pa1.z; As[ac1 * 4 + 3][ar1] = pa1.w;
        Bs[ac0 * 4 + 0][ar0] = pb0.x; Bs[ac0 * 4 + 1][ar0] = pb0.y;
        Bs[ac0 * 4 + 2][ar0] = pb0.z; Bs[ac0 * 4 + 3][ar0] = pb0.w;
        Bs[ac1 * 4 + 0][ar1] = pb1.x; Bs[ac1 * 4 + 1][ar1] = pb1.y;
        Bs[ac1 * 4 + 2][ar1] = pb1.z; Bs[ac1 * 4 + 3][ar1] = pb1.w;
        __syncthreads();

        // issue next tile's LDGs (latency overlapped with compute below)
        if (it + 1 < nIter) {
            int k0 = (it + 1) << 4;
            pa0 = *(const float4*)(a0p + k0);
            pa1 = *(const float4*)(a1p + k0);
            pb0 = *(const float4*)(b0p + k0);
            pb1 = *(const float4*)(b1p + k0);
        }

        #pragma unroll
        for (int kk = 0; kk < 16; kk++) {
            float4 av0 = *(const float4*)&As[kk][ty * 8];
            float4 av1 = *(const float4*)&As[kk][ty * 8 + 4];
            const unsigned long long* bp = (const unsigned long long*)&Bs[kk][tx * 8];
            unsigned long long b2[4];
            #pragma unroll
            for (int j = 0; j < 4; j++) b2[j] = bp[j];
            float a[8] = {av0.x, av0.y, av0.z, av0.w, av1.x, av1.y, av1.z, av1.w};
            #pragma unroll
            for (int i = 0; i < 8; i++) {
                unsigned long long a2 = pack2(a[i], a[i]);
                #pragma unroll
                for (int j = 0; j < 4; j++) acc[i][j] = fma2(a2, b2[j], acc[i][j]);
            }
        }
        __syncthreads();
    }

    #pragma unroll
    for (int i = 0; i < 8; i++) {
        int m = bm + ty * 8 + i;
        float* crow = C + (size_t)m * N + bn + tx * 8;
        #pragma unroll
        for (int j = 0; j < 4; j++) {
            float lo, hi;
            unpack2(acc[i][j], lo, hi);
            int n = bn + tx * 8 + 2 * j;
            lo += bias1[n];
            hi += bias1[n + 1];
            if (bias2) { lo += bias2[n]; hi += bias2[n + 1]; }
            *(float2*)(crow + 2 * j) = make_float2(lo, hi);
        }
    }
}

// ---------------------------------------------------------------------------
// LSTM recurrence: register-resident weights, barrier-free data-as-flag
// exchange (atomicExch publish / ld.volatile canary poll — proven recipe),
// now with:
//  * per-warp chunk gating: warp w polls ONLY its own 128 h-values and starts
//    its matvec immediately (no pre-matvec __syncthreads; chunk is warp-local)
//  * parallel activations: 32 lanes of warp 0 each do one gate's MUFU chain,
//    shfl-gather to lanes 0..7 for the c/h update -> publish issues earlier
// ---------------------------------------------------------------------------
__global__ void __launch_bounds__(256) lstm_recur_kernel(
    const float* __restrict__ Xpre,      // [512*4096] ih part + both biases
    const float* __restrict__ Whh,       // [4096*1024]
    float* __restrict__ Hout,            // [512*1024], canary-filled
    float* __restrict__ out_h,           // [1024] or null
    float* __restrict__ out_c)           // [1024] or null
{
    __shared__ float h_s[HDIM];              // current hidden state (per-warp chunks)
    __shared__ float part_s[32 * 9];         // partials, stride 9 (conflict-free)

    const int tid  = threadIdx.x;
    const int cta  = blockIdx.x;             // 0..127
    const int hb   = cta * 8;
    const int lane = tid & 31;               // row rr
    const int wrp  = tid >> 5;               // h-chunk

    // Row rr -> global row gate*1024 + hb + k   (rr = gate*8 + k)
    const int gate = lane >> 3, k = lane & 7;
    const float* wrow = Whh + (size_t)(gate * 1024 + hb + k) * HDIM + wrp * 128;

    // Load 128 weights into registers as 64 packed f32x2
    unsigned long long w2[64];
    #pragma unroll
    for (int i = 0; i < 32; i++) {
        float4 v = ((const float4*)wrow)[i];
        w2[2 * i]     = pack2(v.x, v.y);
        w2[2 * i + 1] = pack2(v.z, v.w);
    }

    // init own chunk of h to zero (warp-local; no block sync needed)
    ((float4*)h_s)[tid] = make_float4(0.f, 0.f, 0.f, 0.f);
    __syncwarp();

    float c_reg = 0.f;
    float x_cur = 0.f;
    if (wrp == 0)                         // warp0 lane rr holds X[t, row rr]
        x_cur = Xpre[(size_t)gate * 1024 + hb + k];

    const float4* h4 = (const float4*)h_s;

    for (int t = 0; t < T_STEPS; t++) {
        // matvec over own chunk: dot(W_row[128w..], h[128w..]), 4 accumulators
        unsigned long long a0 = 0ull, a1 = 0ull, a2 = 0ull, a3 = 0ull;
        #pragma unroll
        for (int i = 0; i < 32; i += 2) {
            float4 hv0 = h4[wrp * 32 + i];
            float4 hv1 = h4[wrp * 32 + i + 1];
            a0 = fma2(w2[2 * i],     pack2(hv0.x, hv0.y), a0);
            a1 = fma2(w2[2 * i + 1], pack2(hv0.z, hv0.w), a1);
            a2 = fma2(w2[2 * i + 2], pack2(hv1.x, hv1.y), a2);
            a3 = fma2(w2[2 * i + 3], pack2(hv1.z, hv1.w), a3);
        }
        float l0, h0, l1, h1, l2, h2, l3, h3;
        unpack2(a0, l0, h0); unpack2(a1, l1, h1);
        unpack2(a2, l2, h2); unpack2(a3, l3, h3);
        part_s[lane * 9 + wrp] = ((l0 + h0) + (l1 + h1)) + ((l2 + h2) + (l3 + h3));
        __syncthreads();     // all partials visible to warp 0

        if (wrp == 0) {
            // lane rr: full gate pre-activation, parallel MUFU
            float sum = x_cur;
            #pragma unroll
            for (int w = 0; w < 8; w++) sum += part_s[lane * 9 + w];
            float sv  = (gate == 2) ? 2.f * sum : sum;
            float sg  = fsig(sv);
            float val = (gate == 2) ? (2.f * sg - 1.f) : sg;   // tanh for g-gate
            // gather i,f,g,o for h-index k to all lanes (lanes 0..7 use them)
            float i_ = __shfl_sync(0xffffffffu, val, k);
            float f_ = __shfl_sync(0xffffffffu, val, k + 8);
            float g_ = __shfl_sync(0xffffffffu, val, k + 16);
            float o_ = __shfl_sync(0xffffffffu, val, k + 24);
            if (lane < 8) {
                c_reg = f_ * c_reg + i_ * g_;
                float h_new = o_ * (2.f * fsig(2.f * c_reg) - 1.f);
                // publish: LTS-performed RMW, immediately globally visible
                atomicExch(&Hout[(size_t)t * HDIM + hb + lane], h_new);
                if (t == T_STEPS - 1) {
                    if (out_h) out_h[hb + lane] = h_new;
                    if (out_c) out_c[hb + lane] = c_reg;
                }
            }
            // prefetch next step's X (latency hidden behind poll + matvec)
            if (t + 1 < T_STEPS)
                x_cur = Xpre[(size_t)(t + 1) * GDIM + (size_t)gate * 1024 + hb + k];
        }

        // per-warp chunk poll: thread tid polls its own float4 of Hout[t]
        // (chunk w = float4 indices [32w, 32w+32) == tid range of this warp)
        if (t + 1 < T_STEPS) {
            const float4* src = ((const float4*)(Hout + (size_t)t * HDIM)) + tid;
            float fx, fy, fz, fw;
            for (;;) {
                asm volatile("ld.volatile.global.v4.f32 {%0,%1,%2,%3}, [%4];"
                             : "=f"(fx), "=f"(fy), "=f"(fz), "=f"(fw)
                             : "l"(src)
                             : "memory");
                if ((__float_as_uint(fx) != CANARY_U) &
                    (__float_as_uint(fy) != CANARY_U) &
                    (__float_as_uint(fz) != CANARY_U) &
                    (__float_as_uint(fw) != CANARY_U)) break;
            }
            ((float4*)h_s)[tid] = make_float4(fx, fy, fz, fw);
            __syncwarp();    // chunk complete for this warp -> next matvec may read
        }
        // no block-wide sync: warp w's next part_s write is ordered after its
        // poll success, which requires this CTA's own publish, which follows
        // warp 0's part_s reads above.
    }
}

// ---------------------------------------------------------------------------
// Launch
// ---------------------------------------------------------------------------
extern "C" void kernel_launch(void* const* d_in, const int* in_sizes, int n_in,
                              void* d_out, int out_size) {
    const int*   x    = (const int*)  d_in[0];
    const float* emb  = (const float*)d_in[1];
    const float* W_ih = (const float*)d_in[2];
    const float* W_hh = (const float*)d_in[3];
    const float* b_ih = (const float*)d_in[4];
    const float* b_hh = (const float*)d_in[5];
    const float* W_fc = (const float*)d_in[6];
    const float* b_fc = (const float*)d_in[7];

    float* out        = (float*)d_out;
    float* out_scores = out;
    const size_t SC   = (size_t)T_STEPS * VOCAB;
    bool  has_state   = ((size_t)out_size >= SC + 4096);
    float* out_h      = has_state ? out + SC        : nullptr;
    float* out_c      = has_state ? out + SC + 2048 : nullptr;

    void *p_seq, *p_X, *p_H0, *p_H1;
    cudaGetSymbolAddress(&p_seq, g_seq);
    cudaGetSymbolAddress(&p_X,   g_X);
    cudaGetSymbolAddress(&p_H0,  g_H0);
    cudaGetSymbolAddress(&p_H1,  g_H1);
    float* seq = (float*)p_seq;
    float* X   = (float*)p_X;
    float* H0  = (float*)p_H0;
    float* H1  = (float*)p_H1;

    const size_t WSZ = (size_t)GDIM * HDIM;

    // canary-fill H0/H1 (inside the graph; replays re-arm it)
    canary_kernel<<<512, 256>>>();

    embed_kernel<<<T_STEPS, 256>>>(x, emb);

    gemm_nt_bias<<<dim3(GDIM / 128, T_STEPS / 128), 256>>>(
        seq, W_ih, b_ih, b_hh, X, T_STEPS, GDIM, HDIM);

    lstm_recur_kernel<<<NCTA, 256>>>(X, W_hh, H0, out_h, out_c);

    gemm_nt_bias<<<dim3(GDIM / 128, T_STEPS / 128), 256>>>(
        H0, W_ih + WSZ, b_ih + GDIM, b_hh + GDIM, X, T_STEPS, GDIM, HDIM);

    lstm_recur_kernel<<<NCTA, 256>>>(X, W_hh + WSZ, H1,
                                     out_h ? out_h + HDIM : nullptr,
                                     out_c ? out_c + HDIM : nullptr);

    gemm_nt_bias<<<dim3(VOCAB / 128, T_STEPS / 128), 256>>>(
        H1, W_fc, b_fc, nullptr, out_scores, T_STEPS, VOCAB, HDIM);
}